// round 14
// baseline (speedup 1.0000x reference)
#include <cuda_runtime.h>
#include <cuda_fp16.h>
#include <cstdint>
#include <math.h>

// Static problem shape
#define BB 32
#define TT 512
#define DD 512
#define TS 2304          // target_length - 1

#define BM 128           // t tile
#define BN 256           // d tile
#define BK 16            // k per chunk (8 kp words)
#define NCHUNK (TT/BK)   // 32

#define NTHREADS 320     // 256 consumer + 64 producer

// ldmatrix row stride: 8 kp words (32B) padded to 48B (proven rounds 8/10/13)
#define RSTRB 48
#define A_STAGE 6144         // 128 rows * 48B
#define B_STAGE 12288        // 256 rows * 48B
#define B_BASE  (2*A_STAGE)  // 12288
#define DYN_SMEM (B_BASE + 2*B_STAGE)   // 36864

// Device scratch
__device__ float4   g_cus[BB*TT];      // (center, -0.5*sig^2, sig, 0)
__device__ int      g_shift[BB*TT];
__device__ int      g_len[BB*TT];
__device__ float    g_scale[BB*TS];
// xs transposed+packed fp16: word(b,d,ip) = half2(xs[2ip][d], xs[2ip+1][d])
__device__ uint32_t g_xsT[(size_t)BB*DD*(TT/2)];   // 16.8 MB

__device__ __forceinline__ void mma_fp16(float* c, const uint32_t* a, const uint32_t* b) {
    asm volatile(
        "mma.sync.aligned.m16n8k16.row.col.f32.f16.f16.f32 "
        "{%0,%1,%2,%3}, {%4,%5,%6,%7}, {%8,%9}, {%0,%1,%2,%3};"
        : "+f"(c[0]), "+f"(c[1]), "+f"(c[2]), "+f"(c[3])
        : "r"(a[0]), "r"(a[1]), "r"(a[2]), "r"(a[3]), "r"(b[0]), "r"(b[1]));
}
__device__ __forceinline__ void ldm_x4(uint32_t* r, uint32_t addr) {
    asm volatile("ldmatrix.sync.aligned.m8n8.x4.shared.b16 {%0,%1,%2,%3}, [%4];"
                 : "=r"(r[0]), "=r"(r[1]), "=r"(r[2]), "=r"(r[3]) : "r"(addr));
}
__device__ __forceinline__ uint32_t smem_u32(const void* p) {
    uint32_t a;
    asm("{ .reg .u64 t; cvta.to.shared.u64 t, %1; cvt.u32.u64 %0, t; }" : "=r"(a) : "l"(p));
    return a;
}
__device__ __forceinline__ uint32_t pack_h2(float lo, float hi) {
    __half2 h = __floats2half2_rn(lo, hi);
    return *(uint32_t*)&h;
}

// ---------------------------------------------------------------------------
// Kernel 1: prep — cumsum(ds), center, sig = softplus(sigma); packs g_cus
// ---------------------------------------------------------------------------
__global__ void lr_prep_kernel(const int* __restrict__ ds,
                               const float* __restrict__ sigma) {
    __shared__ int s[TT];
    int b = blockIdx.x, t = threadIdx.x;
    int d = ds[b*TT + t];
    s[t] = d;
    __syncthreads();
    for (int off = 1; off < TT; off <<= 1) {
        int v = (t >= off) ? s[t - off] : 0;
        __syncthreads();
        s[t] += v;
        __syncthreads();
    }
    int len = s[t], sh = len - d, idx = b*TT + t;
    g_len[idx] = len;
    g_shift[idx] = sh;
    float x = sigma[idx];
    float sp = (x > 20.f) ? x : log1pf(expf(x));
    float center = 0.5f * (float)d + (float)sh;
    g_cus[idx] = make_float4(center, -0.5f * sp * sp, sp, 0.f);
}

// ---------------------------------------------------------------------------
// Kernel 2: scale[b,t] = row_mass / max(den, 1e-12)   (one warp per (b,t))
// ---------------------------------------------------------------------------
__global__ void lr_scale_kernel() {
    int warp = (blockIdx.x * blockDim.x + threadIdx.x) >> 5;
    int lane = threadIdx.x & 31;
    if (warp >= BB * TS) return;
    int b = warp / TS, t = warp % TS;
    float tr = (float)(t + 1);
    const float4* cu = g_cus + b*TT;
    const int* shp = g_shift + b*TT;
    const int* lnp = g_len + b*TT;
    float den = 0.f; int mass = 0;
    #pragma unroll 4
    for (int i = lane; i < TT; i += 32) {
        float4 u = cu[i];
        float dl = tr - u.x;
        den += __expf(u.y * dl * dl) * u.z;
        mass += (t >= shp[i] && t < lnp[i]) ? 1 : 0;
    }
    #pragma unroll
    for (int o = 16; o > 0; o >>= 1) {
        den  += __shfl_down_sync(0xffffffffu, den, o);
        mass += __shfl_down_sync(0xffffffffu, mass, o);
    }
    if (lane == 0) g_scale[warp] = (float)mass / fmaxf(den, 1e-12f);
}

// ---------------------------------------------------------------------------
// Kernel 3: xs -> g_xsT  (transpose to d-major, fp16 k-pair packed)
// ---------------------------------------------------------------------------
__global__ void lr_cvtT_kernel(const float* __restrict__ xs) {
    __shared__ float tile[32][33];
    int b = blockIdx.z;
    int dblk = blockIdx.x * 32, iblk = blockIdx.y * 32;
    int tx = threadIdx.x, ty = threadIdx.y;     // 32 x 8
    #pragma unroll
    for (int j = 0; j < 32; j += 8)
        tile[ty + j][tx] = xs[((size_t)(b*TT) + iblk + ty + j) * DD + dblk + tx];
    __syncthreads();
    int q = ty * 32 + tx;   // 0..255
    #pragma unroll
    for (int j = 0; j < 2; j++) {
        int v = q + 256 * j;          // 0..511
        int dl = v >> 4;              // 0..31
        int ip = v & 15;              // 0..15
        uint32_t w = pack_h2(tile[2*ip][dl], tile[2*ip + 1][dl]);
        g_xsT[((size_t)(b*DD) + dblk + dl) * (TT/2) + iblk/2 + ip] = w;
    }
}

// ---------------------------------------------------------------------------
// Kernel 4: GEMM, warp-specialized. 320 threads: warps 0-7 consumers
// (tile 128x256, warp 64x64, ldmatrix+MMA only), warps 8-9 producers
// (cp.async B + exp-generate A + stA). One __syncthreads per chunk;
// producers build chunk c+1 while consumers compute chunk c.
// ---------------------------------------------------------------------------
__global__ __launch_bounds__(NTHREADS, 1)
void lr_gemm_mma(float* __restrict__ out) {
    extern __shared__ char sm[];
    __shared__ float4 sCU[TT];          // 8 KB static
    uint32_t sbase = smem_u32(sm);

    int tid = threadIdx.x;
    int wid = tid >> 5, lane = tid & 31;
    int b = blockIdx.z, t0 = blockIdx.y * BM, d0 = blockIdx.x * BN;
    bool producer = (tid >= 256);

    for (int i = tid; i < TT; i += NTHREADS) sCU[i] = g_cus[b*TT + i];

    // ---- producer state ----
    int ptid = tid - 256;                    // 0..63
    const uint32_t* xp = g_xsT + ((size_t)(b*DD + d0)) * (TT/2);
    float psc0 = 0.f, psc1 = 0.f, ptr0 = 0.f, ptr1 = 0.f;
    if (producer) {
        psc0 = g_scale[b*TS + t0 + ptid];
        psc1 = g_scale[b*TS + t0 + ptid + 64];
        ptr0 = (float)(t0 + ptid + 1);
        ptr1 = (float)(t0 + ptid + 64 + 1);
    }
    uint32_t aN0[8], aN1[8];

    auto cpB = [&](int st, int c) {
        #pragma unroll
        for (int it = 0; it < 8; it++) {
            int idx = ptid + 64 * it;        // 0..511 granules
            int row = idx >> 1, h = idx & 1;
            uint32_t dst = sbase + B_BASE + st * B_STAGE + row * RSTRB + h * 16;
            const uint32_t* src = xp + (size_t)row * (TT/2) + c*8 + h*4;
            asm volatile("cp.async.cg.shared.global [%0], [%1], 16;" :: "r"(dst), "l"(src));
        }
        asm volatile("cp.async.commit_group;" ::: "memory");
    };
    auto genStoreA = [&](int c1, int st) {
        int kb = c1 * BK;
        #pragma unroll
        for (int w = 0; w < 8; w++) {
            float4 u0 = sCU[kb + 2*w];
            float4 u1 = sCU[kb + 2*w + 1];
            float d00 = ptr0 - u0.x, d01 = ptr0 - u1.x;
            float d10 = ptr1 - u0.x, d11 = ptr1 - u1.x;
            float e00 = __expf(u0.y * d00 * d00) * u0.z * psc0;
            float e01 = __expf(u1.y * d01 * d01) * u1.z * psc0;
            float e10 = __expf(u0.y * d10 * d10) * u0.z * psc1;
            float e11 = __expf(u1.y * d11 * d11) * u1.z * psc1;
            aN0[w] = pack_h2(e00, e01);
            aN1[w] = pack_h2(e10, e11);
        }
        char* p0 = sm + st * A_STAGE + ptid * RSTRB;
        char* p1 = sm + st * A_STAGE + (ptid + 64) * RSTRB;
        *(uint4*)(p0)      = *(uint4*)&aN0[0];
        *(uint4*)(p0 + 16) = *(uint4*)&aN0[4];
        *(uint4*)(p1)      = *(uint4*)&aN1[0];
        *(uint4*)(p1 + 16) = *(uint4*)&aN1[4];
    };

    // ---- consumer state ----
    int wm = wid >> 2;          // 0..1
    int wn = wid & 3;           // 0..3
    int g = lane >> 2, tig = lane & 3;
    int lr = lane & 7, q = lane >> 3;
    uint32_t aOff = (uint32_t)((wm*64 + lr + (q & 1)*8) * RSTRB + (q >> 1) * 16);
    uint32_t bOff = (uint32_t)(B_BASE + (wn*64 + lr + (q >> 1)*8) * RSTRB + (q & 1) * 16);

    float acc[4][8][4];
    #pragma unroll
    for (int mt = 0; mt < 4; mt++)
        #pragma unroll
        for (int nt = 0; nt < 8; nt++)
            #pragma unroll
            for (int z = 0; z < 4; z++) acc[mt][nt][z] = 0.f;

    __syncthreads();                 // sCU ready

    if (producer) {
        cpB(0, 0);
        genStoreA(0, 0);
        asm volatile("cp.async.wait_group 0;" ::: "memory");
    }
    __syncthreads();                 // chunk 0 staged

    for (int c = 0; c < NCHUNK; c++) {
        int st = c & 1;
        if (producer) {
            if (c + 1 < NCHUNK) {
                cpB(st ^ 1, c + 1);
                genStoreA(c + 1, st ^ 1);
                asm volatile("cp.async.wait_group 0;" ::: "memory");
            }
        } else {
            uint32_t aBase = sbase + st * A_STAGE + aOff;
            uint32_t bBase = sbase + st * B_STAGE + bOff;
            uint32_t a[4][4];
            #pragma unroll
            for (int mt = 0; mt < 4; mt++)
                ldm_x4(a[mt], aBase + mt * 16 * RSTRB);
            #pragma unroll
            for (int nt2 = 0; nt2 < 4; nt2++) {
                uint32_t bb[4];
                ldm_x4(bb, bBase + nt2 * 16 * RSTRB);
                #pragma unroll
                for (int mt = 0; mt < 4; mt++) {
                    mma_fp16(acc[mt][2*nt2],     a[mt], &bb[0]);
                    mma_fp16(acc[mt][2*nt2 + 1], a[mt], &bb[2]);
                }
            }
        }
        __syncthreads();
    }

    // ---- epilogue (consumers only; scale folded into A) ----
    if (!producer) {
        #pragma unroll
        for (int mt = 0; mt < 4; mt++) {
            int r0 = t0 + wm*64 + mt*16 + g;
            float* op0 = out + ((size_t)b*TS + r0) * DD + d0 + wn*64;
            float* op1 = op0 + 8 * DD;
            #pragma unroll
            for (int nt = 0; nt < 8; nt++) {
                int nn = nt*8 + tig*2;
                *(float2*)(op0 + nn) = make_float2(acc[mt][nt][0], acc[mt][nt][1]);
                *(float2*)(op1 + nn) = make_float2(acc[mt][nt][2], acc[mt][nt][3]);
            }
        }
    }
}

// ---------------------------------------------------------------------------
// Launcher. inputs: xs f32 [B,T,D], ds i32 [B,T], sigma f32 [B,T], target i32
// output: f32 [B, 2304, D]
// ---------------------------------------------------------------------------
extern "C" void kernel_launch(void* const* d_in, const int* in_sizes, int n_in,
                              void* d_out, int out_size) {
    const float* xs    = (const float*)d_in[0];
    const int*   ds    = (const int*)  d_in[1];
    const float* sigma = (const float*)d_in[2];
    float* out = (float*)d_out;

    cudaFuncSetAttribute(lr_gemm_mma, cudaFuncAttributeMaxDynamicSharedMemorySize, DYN_SMEM);

    lr_prep_kernel<<<BB, TT>>>(ds, sigma);

    int nwarps = BB * TS;
    int nblk = (nwarps * 32 + 255) / 256;
    lr_scale_kernel<<<nblk, 256>>>();

    dim3 cg(DD / 32, TT / 32, BB);
    lr_cvtT_kernel<<<cg, dim3(32, 8)>>>(xs);

    dim3 grid(DD / BN, TS / BM, BB);   // (2, 18, 32)
    lr_gemm_mma<<<grid, NTHREADS, DYN_SMEM>>>(out);
}

// round 15
// speedup vs baseline: 2.8753x; 2.8753x over previous
#include <cuda_runtime.h>
#include <cuda_fp16.h>
#include <cstdint>
#include <math.h>

// Static problem shape
#define BB 32
#define TT 512
#define DD 512
#define TS 2304          // target_length - 1

#define BM 128           // t tile
#define BN 256           // d tile
#define BK 16            // k per chunk (8 kp words)
#define NCHUNK (TT/BK)   // 32
#define NTILE (TS/BM)    // 18

// ldmatrix row stride: 8 kp words (32B) padded to 48B (proven rounds 8/10/13)
#define RSTRB 48
#define A_STAGE 6144         // 128 rows * 48B
#define B_STAGE 12288        // 256 rows * 48B
#define B_BASE  (2*A_STAGE)  // 12288
#define DYN_SMEM (B_BASE + 2*B_STAGE)   // 36864

// Device scratch
__device__ float4   g_cus[BB*TT];      // (center, -0.5*sig^2, sig, 0)
__device__ int      g_shift[BB*TT];
__device__ int      g_len[BB*TT];
__device__ float    g_scale[BB*TS];
__device__ int      g_crange[BB*NTILE*2];   // per (b,tile): [c_lo, c_hi]
// xs transposed+packed fp16: word(b,d,ip) = half2(xs[2ip][d], xs[2ip+1][d])
__device__ uint32_t g_xsT[(size_t)BB*DD*(TT/2)];   // 16.8 MB

__device__ __forceinline__ void mma_fp16(float* c, const uint32_t* a, const uint32_t* b) {
    asm volatile(
        "mma.sync.aligned.m16n8k16.row.col.f32.f16.f16.f32 "
        "{%0,%1,%2,%3}, {%4,%5,%6,%7}, {%8,%9}, {%0,%1,%2,%3};"
        : "+f"(c[0]), "+f"(c[1]), "+f"(c[2]), "+f"(c[3])
        : "r"(a[0]), "r"(a[1]), "r"(a[2]), "r"(a[3]), "r"(b[0]), "r"(b[1]));
}
__device__ __forceinline__ void ldm_x4(uint32_t* r, uint32_t addr) {
    asm volatile("ldmatrix.sync.aligned.m8n8.x4.shared.b16 {%0,%1,%2,%3}, [%4];"
                 : "=r"(r[0]), "=r"(r[1]), "=r"(r[2]), "=r"(r[3]) : "r"(addr));
}
__device__ __forceinline__ uint32_t smem_u32(const void* p) {
    uint32_t a;
    asm("{ .reg .u64 t; cvta.to.shared.u64 t, %1; cvt.u32.u64 %0, t; }" : "=r"(a) : "l"(p));
    return a;
}
__device__ __forceinline__ uint32_t pack_h2(float lo, float hi) {
    __half2 h = __floats2half2_rn(lo, hi);
    return *(uint32_t*)&h;
}

// ---------------------------------------------------------------------------
// Kernel 1: prep — cumsum(ds), center, sig = softplus(sigma); packs g_cus
// ---------------------------------------------------------------------------
__global__ void lr_prep_kernel(const int* __restrict__ ds,
                               const float* __restrict__ sigma) {
    __shared__ int s[TT];
    int b = blockIdx.x, t = threadIdx.x;
    int d = ds[b*TT + t];
    s[t] = d;
    __syncthreads();
    for (int off = 1; off < TT; off <<= 1) {
        int v = (t >= off) ? s[t - off] : 0;
        __syncthreads();
        s[t] += v;
        __syncthreads();
    }
    int len = s[t], sh = len - d, idx = b*TT + t;
    g_len[idx] = len;
    g_shift[idx] = sh;
    float x = sigma[idx];
    float sp = (x > 20.f) ? x : log1pf(expf(x));
    float center = 0.5f * (float)d + (float)sh;
    g_cus[idx] = make_float4(center, -0.5f * sp * sp, sp, 0.f);
}

// ---------------------------------------------------------------------------
// Kernel 2: scale[b,t] = row_mass / max(den, 1e-12)   (one warp per (b,t))
// ---------------------------------------------------------------------------
__global__ void lr_scale_kernel() {
    int warp = (blockIdx.x * blockDim.x + threadIdx.x) >> 5;
    int lane = threadIdx.x & 31;
    if (warp >= BB * TS) return;
    int b = warp / TS, t = warp % TS;
    float tr = (float)(t + 1);
    const float4* cu = g_cus + b*TT;
    const int* shp = g_shift + b*TT;
    const int* lnp = g_len + b*TT;
    float den = 0.f; int mass = 0;
    #pragma unroll 4
    for (int i = lane; i < TT; i += 32) {
        float4 u = cu[i];
        float dl = tr - u.x;
        den += __expf(u.y * dl * dl) * u.z;
        mass += (t >= shp[i] && t < lnp[i]) ? 1 : 0;
    }
    #pragma unroll
    for (int o = 16; o > 0; o >>= 1) {
        den  += __shfl_down_sync(0xffffffffu, den, o);
        mass += __shfl_down_sync(0xffffffffu, mass, o);
    }
    if (lane == 0) g_scale[warp] = (float)mass / fmaxf(den, 1e-12f);
}

// ---------------------------------------------------------------------------
// Kernel 3: per (b, t-tile) active k-chunk range (conservative sparsity cut).
// Keep i iff  -0.5σ²·dmin² + ln(σ) + ln(max_t scale) >= -25
// (anything that could exceed ~1.4e-11 of row mass; fp16 floor is ~6e-8).
// ---------------------------------------------------------------------------
__global__ void lr_bounds_kernel() {
    __shared__ float sMax[128];
    __shared__ int sMin, sMaxI;
    int tile = blockIdx.x, b = blockIdx.y;
    int t0 = tile * BM;
    int tid = threadIdx.x;       // 256

    if (tid < 128) sMax[tid] = g_scale[b*TS + t0 + tid];
    if (tid == 0) { sMin = TT; sMaxI = -1; }
    __syncthreads();
    for (int o = 64; o > 0; o >>= 1) {
        if (tid < o) sMax[tid] = fmaxf(sMax[tid], sMax[tid + o]);
        __syncthreads();
    }
    float S = logf(fmaxf(sMax[0], 1e-30f));
    float lo = (float)(t0 + 1), hi = (float)(t0 + BM);

    int amin = TT, amax = -1;
    for (int i = tid; i < TT; i += 256) {
        float4 u = g_cus[b*TT + i];
        float thr = 25.0f + logf(u.z) + S;      // >= 0.5σ² dmin² required
        float c = u.x;
        float dmin = (c < lo) ? (lo - c) : ((c > hi) ? (c - hi) : 0.f);
        bool act = (-u.y) * dmin * dmin <= thr; // -u.y = 0.5σ²
        if (act) { amin = min(amin, i); amax = max(amax, i); }
    }
    atomicMin(&sMin, amin);
    atomicMax(&sMaxI, amax);
    __syncthreads();
    if (tid == 0) {
        int cl = (sMin >= TT) ? 0 : sMin / BK;
        int ch = (sMaxI < 0) ? cl : sMaxI / BK;
        if (ch < cl) ch = cl;
        g_crange[(b*NTILE + tile)*2]     = cl;
        g_crange[(b*NTILE + tile)*2 + 1] = ch;
    }
}

// ---------------------------------------------------------------------------
// Kernel 4: xs -> g_xsT  (transpose to d-major, fp16 k-pair packed)
// ---------------------------------------------------------------------------
__global__ void lr_cvtT_kernel(const float* __restrict__ xs) {
    __shared__ float tile[32][33];
    int b = blockIdx.z;
    int dblk = blockIdx.x * 32, iblk = blockIdx.y * 32;
    int tx = threadIdx.x, ty = threadIdx.y;     // 32 x 8
    #pragma unroll
    for (int j = 0; j < 32; j += 8)
        tile[ty + j][tx] = xs[((size_t)(b*TT) + iblk + ty + j) * DD + dblk + tx];
    __syncthreads();
    int q = ty * 32 + tx;   // 0..255
    #pragma unroll
    for (int j = 0; j < 2; j++) {
        int v = q + 256 * j;          // 0..511
        int dl = v >> 4;              // 0..31
        int ip = v & 15;              // 0..15
        uint32_t w = pack_h2(tile[2*ip][dl], tile[2*ip + 1][dl]);
        g_xsT[((size_t)(b*DD) + dblk + dl) * (TT/2) + iblk/2 + ip] = w;
    }
}

// ---------------------------------------------------------------------------
// Kernel 5: GEMM. CTA 128x256, 8 warps (2x4), warp 64x64. BK=16.
// Round-10 proven pipeline + fragment maps; iterates only active chunks
// [c_lo, c_hi] from g_crange.
// ---------------------------------------------------------------------------
__global__ __launch_bounds__(256, 1)
void lr_gemm_mma(float* __restrict__ out) {
    extern __shared__ char sm[];
    __shared__ float4 sCU[TT];          // 8 KB static
    uint32_t sbase = smem_u32(sm);

    int tid = threadIdx.x;
    int wid = tid >> 5, lane = tid & 31;
    int g = lane >> 2, tig = lane & 3;
    int wm = wid >> 2;          // 0..1
    int wn = wid & 3;           // 0..3
    int b = blockIdx.z, t0 = blockIdx.y * BM, d0 = blockIdx.x * BN;

    int c_lo = g_crange[(b*NTILE + blockIdx.y)*2];
    int c_hi = g_crange[(b*NTILE + blockIdx.y)*2 + 1];

    const uint32_t* xp = g_xsT + ((size_t)(b*DD + d0)) * (TT/2);

    // ---- cp.async B (round-8/10 mapping): 256 rows x 32B; 512 granules ----
    auto cpB = [&](int st, int c) {
        #pragma unroll
        for (int it = 0; it < 2; it++) {
            int idx = tid + 256 * it;
            int row = idx >> 1, h = idx & 1;
            uint32_t dst = sbase + B_BASE + st * B_STAGE + row * RSTRB + h * 16;
            const uint32_t* src = xp + (size_t)row * (TT/2) + c*8 + h*4;
            asm volatile("cp.async.cg.shared.global [%0], [%1], 16;" :: "r"(dst), "l"(src));
        }
        asm volatile("cp.async.commit_group;" ::: "memory");
    };

    // ---- A generation (round-10 verified; linear layout, scale folded) ----
    int arow = tid >> 1, ah = tid & 1;
    float myscale = g_scale[b*TS + t0 + arow];
    float trow = (float)(t0 + arow + 1);
    uint32_t aNext[4];
    auto genA = [&](int c1) {
        int kb = c1 * BK;
        #pragma unroll
        for (int j = 0; j < 4; j++) {
            int w = ah*4 + j;                    // word 0..7, k = 2w, 2w+1
            float4 u0 = sCU[kb + 2*w];
            float4 u1 = sCU[kb + 2*w + 1];
            float dl0 = trow - u0.x, dl1 = trow - u1.x;
            float e0 = __expf(u0.y * dl0 * dl0) * u0.z * myscale;
            float e1 = __expf(u1.y * dl1 * dl1) * u1.z * myscale;
            aNext[j] = pack_h2(e0, e1);
        }
    };
    auto stA = [&](int st) {
        *(uint4*)(sm + st * A_STAGE + arow * RSTRB + ah * 16) = *(uint4*)aNext;
    };

    // ---- ldmatrix per-lane offsets (round-8/10 verified, RSTRB=48) ----
    int lr = lane & 7, q = lane >> 3;
    uint32_t aOff = (uint32_t)((wm*64 + lr + (q & 1)*8) * RSTRB + (q >> 1) * 16);
    uint32_t bOff = (uint32_t)(B_BASE + (wn*64 + lr + (q >> 1)*8) * RSTRB + (q & 1) * 16);

    float acc[4][8][4];
    #pragma unroll
    for (int mt = 0; mt < 4; mt++)
        #pragma unroll
        for (int nt = 0; nt < 8; nt++)
            #pragma unroll
            for (int z = 0; z < 4; z++) acc[mt][nt][z] = 0.f;

    // ---- prologue (round-10 ordering, starting at c_lo) ----
    cpB(c_lo & 1, c_lo);
    for (int i = tid; i < TT; i += 256) sCU[i] = g_cus[b*TT + i];
    __syncthreads();                 // sCU ready
    genA(c_lo);
    stA(c_lo & 1);
    asm volatile("cp.async.wait_group 0;" ::: "memory");
    __syncthreads();

    for (int c = c_lo; c <= c_hi; c++) {
        int st = c & 1;
        if (c < c_hi) { cpB(st ^ 1, c + 1); genA(c + 1); }

        uint32_t aBase = sbase + st * A_STAGE + aOff;
        uint32_t bBase = sbase + st * B_STAGE + bOff;
        uint32_t a[4][4];
        #pragma unroll
        for (int mt = 0; mt < 4; mt++)
            ldm_x4(a[mt], aBase + mt * 16 * RSTRB);
        #pragma unroll
        for (int nt2 = 0; nt2 < 4; nt2++) {
            uint32_t bb[4];
            ldm_x4(bb, bBase + nt2 * 16 * RSTRB);
            #pragma unroll
            for (int mt = 0; mt < 4; mt++) {
                mma_fp16(acc[mt][2*nt2],     a[mt], &bb[0]);
                mma_fp16(acc[mt][2*nt2 + 1], a[mt], &bb[2]);
            }
        }

        if (c < c_hi) {
            stA(st ^ 1);
            asm volatile("cp.async.wait_group 0;" ::: "memory");
        }
        __syncthreads();
    }

    // ---- epilogue (scale already folded into A) ----
    #pragma unroll
    for (int mt = 0; mt < 4; mt++) {
        int r0 = t0 + wm*64 + mt*16 + g;
        float* op0 = out + ((size_t)b*TS + r0) * DD + d0 + wn*64;
        float* op1 = op0 + 8 * DD;
        #pragma unroll
        for (int nt = 0; nt < 8; nt++) {
            int nn = nt*8 + tig*2;
            *(float2*)(op0 + nn) = make_float2(acc[mt][nt][0], acc[mt][nt][1]);
            *(float2*)(op1 + nn) = make_float2(acc[mt][nt][2], acc[mt][nt][3]);
        }
    }
}

// ---------------------------------------------------------------------------
// Launcher. inputs: xs f32 [B,T,D], ds i32 [B,T], sigma f32 [B,T], target i32
// output: f32 [B, 2304, D]
// ---------------------------------------------------------------------------
extern "C" void kernel_launch(void* const* d_in, const int* in_sizes, int n_in,
                              void* d_out, int out_size) {
    const float* xs    = (const float*)d_in[0];
    const int*   ds    = (const int*)  d_in[1];
    const float* sigma = (const float*)d_in[2];
    float* out = (float*)d_out;

    cudaFuncSetAttribute(lr_gemm_mma, cudaFuncAttributeMaxDynamicSharedMemorySize, DYN_SMEM);

    lr_prep_kernel<<<BB, TT>>>(ds, sigma);

    int nwarps = BB * TS;
    int nblk = (nwarps * 32 + 255) / 256;
    lr_scale_kernel<<<nblk, 256>>>();

    dim3 bg(NTILE, BB);
    lr_bounds_kernel<<<bg, 256>>>();

    dim3 cg(DD / 32, TT / 32, BB);
    lr_cvtT_kernel<<<cg, dim3(32, 8)>>>(xs);

    dim3 grid(DD / BN, TS / BM, BB);   // (2, 18, 32)
    lr_gemm_mma<<<grid, 256, DYN_SMEM>>>(out);
}